// round 15
// baseline (speedup 1.0000x reference)
#include <cuda_runtime.h>

#define BATCH 64
#define CH 3
#define IMG 640
#define PH 20
#define POOL 32
#define KDIM 1200
#define NQ 300
#define NCCOLS 84
#define NTOT 25200          // NQ * NCCOLS
#define NHALF 12600         // NTOT / 2 (two cols per thread)
#define TOPK 150
#define BT 32               // batch tile per GEMM block (2 b-sweeps, W read 2x)
#define PAIRS (BT / 2)      // 16 f32x2-packed batch pairs per block
#define NPAIRS (BATCH / 2)  // 32 total pairs
#define KCMAX 248           // Eigen threaded kc (FROZEN: matches reference bits)
#define NPANEL 5            // 248,248,248,248,208

__device__ unsigned long long g_pp[KDIM * NPAIRS];   // packed pairs [k][pair]
__device__ float g_part[NPANEL][BATCH * NTOT];       // per-panel partials, 32 MB
__device__ int   g_cnt[NPANEL];                      // slice-completion counters

typedef unsigned long long ull;

__device__ __forceinline__ ull pack2(float lo, float hi) {
    ull r; asm("mov.b64 %0, {%1, %2};" : "=l"(r) : "f"(lo), "f"(hi)); return r;
}
__device__ __forceinline__ ull dup2(float w) {
    ull r; asm("mov.b64 %0, {%1, %1};" : "=l"(r) : "f"(w)); return r;
}
__device__ __forceinline__ void fma2(ull& acc, ull a, ull b) {
    asm("fma.rn.f32x2 %0, %1, %2, %0;" : "+l"(acc) : "l"(a), "l"(b));
}
__device__ __forceinline__ void unpack2(ull v, float& lo, float& hi) {
    asm("mov.b64 {%0, %1}, %2;" : "=f"(lo), "=f"(hi) : "l"(v));
}

// ---------------------------------------------------------------------------
// Init: zero the slice counters (deterministic per call / per graph replay).
// ---------------------------------------------------------------------------
__global__ void init_kernel() {
    if (threadIdx.x < NPANEL) g_cnt[threadIdx.x] = 0;
}

// ---------------------------------------------------------------------------
// Fused pool+GEMM, grid (99, 2, 6). blockIdx.z==0 -> POOL role (lowest bids,
// wave-1 resident): all 76800 cells in k-major order; per cell:
//   pooled = fl( exact_int_sum * fl(1/261120) )   (FROZEN NUMERICS)
// written into packed layout ((float*)g_pp)[k*64+b]; __threadfence then
// atomicAdd on the cell's slice counter.
// z in 1..5 -> GEMM role, Eigen kc=248 panel pan=z-1 (FROZEN chains, BT=32,
// 2-column register blocking): spin (nanosleep, bounded) until slice
// counter == 64*len, then tile-fill via __ldcg (L2-coherent with the fence).
// Overlap: GEMM starts ~12us in while the pool keeps streaming HBM.
// ---------------------------------------------------------------------------
__global__ void __launch_bounds__(128) fused_kernel(
        const float* __restrict__ W, const int* __restrict__ x) {

    if (blockIdx.z == 0) {
        // ---------------- POOL role ----------------
        const int nwarps = 99 * 2 * 4;                       // 792
        int wid = (blockIdx.y * 99 + blockIdx.x) * 4 + (threadIdx.x >> 5);
        int lane = threadIdx.x & 31;
        int rowoff = lane >> 3;            // 0..3
        int coloff = (lane & 7) * 4;       // 0,4,..,28 (ints)
        const int ncells = KDIM * BATCH;   // k-major: cell = kk*64 + b
        for (int cell = wid; cell < ncells; cell += nwarps) {
            int kk = cell >> 6;            // / BATCH
            int b  = cell & 63;            // % BATCH
            int c   = kk / 400;            // kk = c*400 + ph*20 + pw
            int rem = kk % 400;
            int ph = rem / 20;
            int pw = rem % 20;
            int c_in = 2 - c;              // BGR flip
            const int* base = x + (((long)(b * CH + c_in) * IMG + ph * POOL) * IMG)
                                + pw * POOL;
            int sum = 0;
#pragma unroll
            for (int r = 0; r < POOL; r += 4) {
                int4 v = *(const int4*)(base + (r + rowoff) * IMG + coloff);
                sum += v.x + v.y + v.z + v.w;
            }
#pragma unroll
            for (int s = 16; s; s >>= 1) sum += __shfl_xor_sync(0xffffffffu, sum, s);
            if (lane == 0) {
                ((float*)g_pp)[cell] = (float)sum * (1.0f / 261120.0f);
                __threadfence();           // publish before signaling
                int sl = kk / KCMAX; if (sl > 4) sl = 4;
                atomicAdd(&g_cnt[sl], 1);
            }
        }
        return;
    }

    // ---------------- GEMM role ----------------
    __shared__ ull p_s[KCMAX][PAIRS];        // 31.7 KB
    int pan = blockIdx.z - 1;
    int k0  = pan * KCMAX;
    int len = (pan == NPANEL - 1) ? (KDIM - 4 * KCMAX) : KCMAX;   // 208 last
    int n0 = blockIdx.x * 128 + threadIdx.x; // col 0: [0, 12600)
    int pbase = blockIdx.y * PAIRS;          // this block's 16 pairs
    bool active = (n0 < NHALF);
    int n1 = n0 + NHALF;                     // col 1: [12600, 25200)

    // spin-gate: wait for this panel's pool slice (bounded; pool is wave-1)
    if (threadIdx.x == 0) {
        int target = len * BATCH;
        long guard = 0;
        while (atomicAdd(&g_cnt[pan], 0) < target && guard < 2000000000L) {
            __nanosleep(128);
            guard++;
        }
    }
    __syncthreads();

    // coalesced tile fill; __ldcg = L2 read, coherent with writer's fence
    for (int idx = threadIdx.x; idx < len * PAIRS; idx += 128) {
        int kk = idx >> 4, pp = idx & 15;
        p_s[kk][pp] = __ldcg(&g_pp[(k0 + kk) * NPAIRS + pbase + pp]);
    }
    __syncthreads();

    ull acc0[PAIRS], acc1[PAIRS];
#pragma unroll
    for (int i = 0; i < PAIRS; i++) { acc0[i] = 0ull; acc1[i] = 0ull; }

    if (active) {
        const float* wpa = W + (long)k0 * NTOT + n0;
        const float* wpb = W + (long)k0 * NTOT + n1;
        for (int kk = 0; kk < len; kk += 4) {
            float a0 = wpa[0];
            float a1 = wpa[NTOT];
            float a2 = wpa[2 * NTOT];
            float a3 = wpa[3 * NTOT];
            float c0 = wpb[0];
            float c1 = wpb[NTOT];
            float c2 = wpb[2 * NTOT];
            float c3 = wpb[3 * NTOT];
            wpa += 4 * (long)NTOT;
            wpb += 4 * (long)NTOT;
            ull A0 = dup2(a0), A1 = dup2(a1), A2 = dup2(a2), A3 = dup2(a3);
            ull C0 = dup2(c0), C1 = dup2(c1), C2 = dup2(c2), C3 = dup2(c3);
#pragma unroll
            for (int h = 0; h < PAIRS / 2; h++) {
                ulonglong2 q0 = *(const ulonglong2*)&p_s[kk + 0][2 * h];
                ulonglong2 q1 = *(const ulonglong2*)&p_s[kk + 1][2 * h];
                ulonglong2 q2 = *(const ulonglong2*)&p_s[kk + 2][2 * h];
                ulonglong2 q3 = *(const ulonglong2*)&p_s[kk + 3][2 * h];
                // strictly ascending k per accumulator chain (FROZEN)
                fma2(acc0[2 * h], q0.x, A0);
                fma2(acc0[2 * h], q1.x, A1);
                fma2(acc0[2 * h], q2.x, A2);
                fma2(acc0[2 * h], q3.x, A3);
                fma2(acc0[2 * h + 1], q0.y, A0);
                fma2(acc0[2 * h + 1], q1.y, A1);
                fma2(acc0[2 * h + 1], q2.y, A2);
                fma2(acc0[2 * h + 1], q3.y, A3);
                fma2(acc1[2 * h], q0.x, C0);
                fma2(acc1[2 * h], q1.x, C1);
                fma2(acc1[2 * h], q2.x, C2);
                fma2(acc1[2 * h], q3.x, C3);
                fma2(acc1[2 * h + 1], q0.y, C0);
                fma2(acc1[2 * h + 1], q1.y, C1);
                fma2(acc1[2 * h + 1], q2.y, C2);
                fma2(acc1[2 * h + 1], q3.y, C3);
            }
        }

        float* part = g_part[pan];
#pragma unroll
        for (int pp = 0; pp < PAIRS; pp++) {
            long rA = (long)(2 * (pbase + pp))     * NTOT;
            long rB = (long)(2 * (pbase + pp) + 1) * NTOT;
            float ya, yb;
            unpack2(acc0[pp], ya, yb);
            part[rA + n0] = ya; part[rB + n0] = yb;
            unpack2(acc1[pp], ya, yb);
            part[rA + n1] = ya; part[rB + n1] = yb;
        }
    }
}

// ---------------------------------------------------------------------------
// Fused epilogue: one block per batch (320 threads).
// Phase 1 (10 warps): per q, y = ((((p0+p1)+p2)+p3)+p4) (FROZEN merge), then
// max/argmax over 80 class cols (ties -> lower index, matches jnp.argmax).
// Phase 2: rank-count top-150 (descending, ties by lower index — matches
// lax.top_k); boxes merged from partials in FROZEN order on output.
// ---------------------------------------------------------------------------
__global__ void __launch_bounds__(320) epilogue_kernel(float* __restrict__ out) {
    __shared__ float s_score[NQ];
    __shared__ int   s_id[NQ];
    int b = blockIdx.x;
    int wid = threadIdx.x >> 5;      // 0..9
    int lane = threadIdx.x & 31;

    for (int q = wid; q < NQ; q += 10) {
        long rowoff = ((long)b * NQ + q) * NCCOLS;
        float best = -3.4e38f;
        int bidx = 0x7fffffff;
        for (int j = lane; j < 80; j += 32) {
            long e = rowoff + 4 + j;
            float v = g_part[0][e];          // FROZEN merge order
            v = v + g_part[1][e];
            v = v + g_part[2][e];
            v = v + g_part[3][e];
            v = v + g_part[4][e];
            if (v > best) { best = v; bidx = j; }
        }
#pragma unroll
        for (int s = 16; s; s >>= 1) {
            float ov = __shfl_xor_sync(0xffffffffu, best, s);
            int   oi = __shfl_xor_sync(0xffffffffu, bidx, s);
            if (ov > best || (ov == best && oi < bidx)) { best = ov; bidx = oi; }
        }
        if (lane == 0) { s_score[q] = best; s_id[q] = bidx; }
    }
    __syncthreads();

    int q = threadIdx.x;
    if (q < NQ) {
        float v = s_score[q];
        int rank = 0;
        for (int j = 0; j < NQ; j++) {
            float u = s_score[j];
            rank += (u > v) || (u == v && j < q);
        }
        if (rank < TOPK) {
            float* o = out + (long)(b * TOPK + rank) * 6;
            long rowoff = ((long)b * NQ + q) * NCCOLS;
#pragma unroll
            for (int c = 0; c < 4; c++) {
                float bx = g_part[0][rowoff + c];    // FROZEN merge order
                bx = bx + g_part[1][rowoff + c];
                bx = bx + g_part[2][rowoff + c];
                bx = bx + g_part[3][rowoff + c];
                bx = bx + g_part[4][rowoff + c];
                o[c] = bx;
            }
            o[4] = v;
            o[5] = (float)s_id[q];
        }
    }
}

extern "C" void kernel_launch(void* const* d_in, const int* in_sizes, int n_in,
                              void* d_out, int out_size) {
    const int*   x = (const int*)d_in[0];
    const float* W = (const float*)d_in[1];
    float* out = (float*)d_out;

    init_kernel<<<1, 32>>>();

    dim3 g(99, BATCH / BT, NPANEL + 1);   // (99, 2, 6): z=0 pool, z=1..5 panels
    fused_kernel<<<g, 128>>>(W, x);

    epilogue_kernel<<<BATCH, 320>>>(out);
}

// round 16
// speedup vs baseline: 1.3898x; 1.3898x over previous
#include <cuda_runtime.h>

#define BATCH 64
#define CH 3
#define IMG 640
#define PH 20
#define POOL 32
#define KDIM 1200
#define NQ 300
#define NCCOLS 84
#define NTOT 25200          // NQ * NCCOLS
#define NHALF 12600         // NTOT / 2 (two cols per thread)
#define TOPK 150
#define BT 32               // batch tile per GEMM block (2 b-sweeps)
#define PAIRS (BT / 2)      // 16 f32x2-packed batch pairs per block
#define NPAIRS (BATCH / 2)  // 32 total pairs
#define KCMAX 248           // Eigen threaded kc (FROZEN: matches reference bits)
#define NPANEL 5            // 248,248,248,248,208

__device__ unsigned long long g_pp[KDIM * NPAIRS];   // packed pairs [k][pair]
__device__ float g_part[NPANEL][BATCH * NTOT];       // per-panel partials, 32 MB

typedef unsigned long long ull;

__device__ __forceinline__ ull pack2(float lo, float hi) {
    ull r; asm("mov.b64 %0, {%1, %2};" : "=l"(r) : "f"(lo), "f"(hi)); return r;
}
__device__ __forceinline__ ull dup2(float w) {
    ull r; asm("mov.b64 %0, {%1, %1};" : "=l"(r) : "f"(w)); return r;
}
__device__ __forceinline__ void fma2(ull& acc, ull a, ull b) {
    asm("fma.rn.f32x2 %0, %1, %2, %0;" : "+l"(acc) : "l"(a), "l"(b));
}
__device__ __forceinline__ void unpack2(ull v, float& lo, float& hi) {
    asm("mov.b64 {%0, %1}, %2;" : "=f"(lo), "=f"(hi) : "l"(v));
}

// ---------------------------------------------------------------------------
// Kernel 1 (FROZEN NUMERICS): 32x32 mean pool + BGR flip.
// pooled = fl( exact_int_sum * fl(1/261120) ); int sum < 2^24 exact.
// One warp per pooled cell, writing DIRECTLY into the packed GEMM layout
// ((float*)g_pp)[k*64 + b]  (pair pp = batches (2pp, 2pp+1)).
// At HBM roofline (82%, compulsory 314 MB) — frozen structure.
// ---------------------------------------------------------------------------
__global__ void pool_kernel(const int* __restrict__ x) {
    int warp = (blockIdx.x * blockDim.x + threadIdx.x) >> 5;
    int lane = threadIdx.x & 31;
    if (warp >= BATCH * CH * PH * PH) return;
    int pw = warp % PH;
    int ph = (warp / PH) % PH;
    int c  = (warp / (PH * PH)) % CH;
    int b  = warp / (PH * PH * CH);
    int c_in = 2 - c;  // BGR flip
    const int* base = x + (((long)(b * CH + c_in) * IMG + ph * POOL) * IMG) + pw * POOL;
    int rowoff = lane >> 3;        // 0..3
    int coloff = (lane & 7) * 4;   // 0,4,..,28 (ints)
    int sum = 0;
#pragma unroll
    for (int r = 0; r < POOL; r += 4) {
        int4 v = *(const int4*)(base + (r + rowoff) * IMG + coloff);
        sum += v.x + v.y + v.z + v.w;
    }
#pragma unroll
    for (int s = 16; s; s >>= 1) sum += __shfl_xor_sync(0xffffffffu, sum, s);
    if (lane == 0) {
        int kk = c * (PH * PH) + ph * PH + pw;
        ((float*)g_pp)[kk * BATCH + b] = (float)sum * (1.0f / 261120.0f);
    }
}

// ---------------------------------------------------------------------------
// Kernel 2 (FROZEN NUMERICS per chain): all 5 Eigen kc=248 panels run
// CONCURRENTLY (grid.z = panel). Each block: ascending-k fused-FMA chain
// per (batch, n) from 0 over its panel -> g_part[panel]. 2-column register
// blocking (n, n+12600), BT=32. 990 blocks -> ~16 warps/SM.
// ---------------------------------------------------------------------------
__global__ void __launch_bounds__(128) gemm_panel_kernel(const float* __restrict__ W) {
    __shared__ ull p_s[KCMAX][PAIRS];        // 31.7 KB
    int pan = blockIdx.z;
    int k0  = pan * KCMAX;
    int len = (pan == NPANEL - 1) ? (KDIM - 4 * KCMAX) : KCMAX;   // 208 last
    int n0 = blockIdx.x * 128 + threadIdx.x; // col 0: [0, 12600)
    int pbase = blockIdx.y * PAIRS;          // this block's 16 pairs
    bool active = (n0 < NHALF);
    int n1 = n0 + NHALF;                     // col 1: [12600, 25200)

    // coalesced tile fill: 128 B contiguous per k row
    for (int idx = threadIdx.x; idx < len * PAIRS; idx += 128) {
        int kk = idx >> 4, pp = idx & 15;
        p_s[kk][pp] = g_pp[(k0 + kk) * NPAIRS + pbase + pp];
    }
    __syncthreads();

    ull acc0[PAIRS], acc1[PAIRS];
#pragma unroll
    for (int i = 0; i < PAIRS; i++) { acc0[i] = 0ull; acc1[i] = 0ull; }

    if (active) {
        const float* wpa = W + (long)k0 * NTOT + n0;
        const float* wpb = W + (long)k0 * NTOT + n1;
        for (int kk = 0; kk < len; kk += 4) {
            float a0 = wpa[0];
            float a1 = wpa[NTOT];
            float a2 = wpa[2 * NTOT];
            float a3 = wpa[3 * NTOT];
            float c0 = wpb[0];
            float c1 = wpb[NTOT];
            float c2 = wpb[2 * NTOT];
            float c3 = wpb[3 * NTOT];
            wpa += 4 * (long)NTOT;
            wpb += 4 * (long)NTOT;
            ull A0 = dup2(a0), A1 = dup2(a1), A2 = dup2(a2), A3 = dup2(a3);
            ull C0 = dup2(c0), C1 = dup2(c1), C2 = dup2(c2), C3 = dup2(c3);
#pragma unroll
            for (int h = 0; h < PAIRS / 2; h++) {
                ulonglong2 q0 = *(const ulonglong2*)&p_s[kk + 0][2 * h];
                ulonglong2 q1 = *(const ulonglong2*)&p_s[kk + 1][2 * h];
                ulonglong2 q2 = *(const ulonglong2*)&p_s[kk + 2][2 * h];
                ulonglong2 q3 = *(const ulonglong2*)&p_s[kk + 3][2 * h];
                // strictly ascending k per accumulator chain (FROZEN)
                fma2(acc0[2 * h], q0.x, A0);
                fma2(acc0[2 * h], q1.x, A1);
                fma2(acc0[2 * h], q2.x, A2);
                fma2(acc0[2 * h], q3.x, A3);
                fma2(acc0[2 * h + 1], q0.y, A0);
                fma2(acc0[2 * h + 1], q1.y, A1);
                fma2(acc0[2 * h + 1], q2.y, A2);
                fma2(acc0[2 * h + 1], q3.y, A3);
                fma2(acc1[2 * h], q0.x, C0);
                fma2(acc1[2 * h], q1.x, C1);
                fma2(acc1[2 * h], q2.x, C2);
                fma2(acc1[2 * h], q3.x, C3);
                fma2(acc1[2 * h + 1], q0.y, C0);
                fma2(acc1[2 * h + 1], q1.y, C1);
                fma2(acc1[2 * h + 1], q2.y, C2);
                fma2(acc1[2 * h + 1], q3.y, C3);
            }
        }

        float* part = g_part[pan];
#pragma unroll
        for (int pp = 0; pp < PAIRS; pp++) {
            long rA = (long)(2 * (pbase + pp))     * NTOT;
            long rB = (long)(2 * (pbase + pp) + 1) * NTOT;
            float ya, yb;
            unpack2(acc0[pp], ya, yb);
            part[rA + n0] = ya; part[rB + n0] = yb;
            unpack2(acc1[pp], ya, yb);
            part[rA + n1] = ya; part[rB + n1] = yb;
        }
    }
}

// ---------------------------------------------------------------------------
// Kernel 3 (fused epilogue): one block per batch (320 threads).
// Phase 1 (10 warps): per q, y = ((((p0+p1)+p2)+p3)+p4) (FROZEN merge), then
// max/argmax over 80 class cols (ties -> lower index, matches jnp.argmax).
// Phase 2: rank-count top-150 (descending, ties by lower index — matches
// lax.top_k); boxes merged from partials in FROZEN order on output.
// ---------------------------------------------------------------------------
__global__ void __launch_bounds__(320) epilogue_kernel(float* __restrict__ out) {
    __shared__ float s_score[NQ];
    __shared__ int   s_id[NQ];
    int b = blockIdx.x;
    int wid = threadIdx.x >> 5;      // 0..9
    int lane = threadIdx.x & 31;

    for (int q = wid; q < NQ; q += 10) {
        long rowoff = ((long)b * NQ + q) * NCCOLS;
        float best = -3.4e38f;
        int bidx = 0x7fffffff;
        for (int j = lane; j < 80; j += 32) {
            long e = rowoff + 4 + j;
            float v = g_part[0][e];          // FROZEN merge order
            v = v + g_part[1][e];
            v = v + g_part[2][e];
            v = v + g_part[3][e];
            v = v + g_part[4][e];
            if (v > best) { best = v; bidx = j; }
        }
#pragma unroll
        for (int s = 16; s; s >>= 1) {
            float ov = __shfl_xor_sync(0xffffffffu, best, s);
            int   oi = __shfl_xor_sync(0xffffffffu, bidx, s);
            if (ov > best || (ov == best && oi < bidx)) { best = ov; bidx = oi; }
        }
        if (lane == 0) { s_score[q] = best; s_id[q] = bidx; }
    }
    __syncthreads();

    int q = threadIdx.x;
    if (q < NQ) {
        float v = s_score[q];
        int rank = 0;
        for (int j = 0; j < NQ; j++) {
            float u = s_score[j];
            rank += (u > v) || (u == v && j < q);
        }
        if (rank < TOPK) {
            float* o = out + (long)(b * TOPK + rank) * 6;
            long rowoff = ((long)b * NQ + q) * NCCOLS;
#pragma unroll
            for (int c = 0; c < 4; c++) {
                float bx = g_part[0][rowoff + c];    // FROZEN merge order
                bx = bx + g_part[1][rowoff + c];
                bx = bx + g_part[2][rowoff + c];
                bx = bx + g_part[3][rowoff + c];
                bx = bx + g_part[4][rowoff + c];
                o[c] = bx;
            }
            o[4] = v;
            o[5] = (float)s_id[q];
        }
    }
}

extern "C" void kernel_launch(void* const* d_in, const int* in_sizes, int n_in,
                              void* d_out, int out_size) {
    const int*   x = (const int*)d_in[0];
    const float* W = (const float*)d_in[1];
    float* out = (float*)d_out;

    pool_kernel<<<(BATCH * CH * PH * PH) / 8, 256>>>(x);

    dim3 gg((NHALF + 127) / 128, BATCH / BT, NPANEL);   // (99, 2, 5) = 990 blocks
    gemm_panel_kernel<<<gg, 128>>>(W);

    epilogue_kernel<<<BATCH, 320>>>(out);
}

// round 17
// speedup vs baseline: 1.7139x; 1.2332x over previous
#include <cuda_runtime.h>

#define BATCH 64
#define CH 3
#define IMG 640
#define PH 20
#define POOL 32
#define KDIM 1200
#define NQ 300
#define NCCOLS 84
#define NTOT 25200          // NQ * NCCOLS
#define NHALF 12600         // NTOT / 2 (two cols per thread)
#define TOPK 150
#define BT 32               // batch tile per GEMM block (2 b-sweeps)
#define PAIRS (BT / 2)      // 16 f32x2-packed batch pairs per block
#define NPAIRS (BATCH / 2)  // 32 total pairs
#define KCMAX 248           // Eigen threaded kc (FROZEN: matches reference bits)
#define NPANEL 5            // 248,248,248,248,208

__device__ unsigned long long g_pp[KDIM * NPAIRS];   // packed pairs [k][pair]
__device__ float g_part[NPANEL][BATCH * NTOT];       // per-panel partials, 32 MB
__device__ float g_scores[BATCH * NQ];
__device__ int   g_ids[BATCH * NQ];

typedef unsigned long long ull;

__device__ __forceinline__ ull pack2(float lo, float hi) {
    ull r; asm("mov.b64 %0, {%1, %2};" : "=l"(r) : "f"(lo), "f"(hi)); return r;
}
__device__ __forceinline__ ull dup2(float w) {
    ull r; asm("mov.b64 %0, {%1, %1};" : "=l"(r) : "f"(w)); return r;
}
__device__ __forceinline__ void fma2(ull& acc, ull a, ull b) {
    asm("fma.rn.f32x2 %0, %1, %2, %0;" : "+l"(acc) : "l"(a), "l"(b));
}
__device__ __forceinline__ void unpack2(ull v, float& lo, float& hi) {
    asm("mov.b64 {%0, %1}, %2;" : "=f"(lo), "=f"(hi) : "l"(v));
}

// ---------------------------------------------------------------------------
// Kernel 1 (FROZEN NUMERICS): 32x32 mean pool + BGR flip.
// pooled = fl( exact_int_sum * fl(1/261120) ); int sum < 2^24 exact.
// One warp per pooled cell, writing DIRECTLY into the packed GEMM layout
// ((float*)g_pp)[k*64 + b]. At HBM roofline (83%) — frozen structure.
// ---------------------------------------------------------------------------
__global__ void pool_kernel(const int* __restrict__ x) {
    int warp = (blockIdx.x * blockDim.x + threadIdx.x) >> 5;
    int lane = threadIdx.x & 31;
    if (warp >= BATCH * CH * PH * PH) return;
    int pw = warp % PH;
    int ph = (warp / PH) % PH;
    int c  = (warp / (PH * PH)) % CH;
    int b  = warp / (PH * PH * CH);
    int c_in = 2 - c;  // BGR flip
    const int* base = x + (((long)(b * CH + c_in) * IMG + ph * POOL) * IMG) + pw * POOL;
    int rowoff = lane >> 3;        // 0..3
    int coloff = (lane & 7) * 4;   // 0,4,..,28 (ints)
    int sum = 0;
#pragma unroll
    for (int r = 0; r < POOL; r += 4) {
        int4 v = *(const int4*)(base + (r + rowoff) * IMG + coloff);
        sum += v.x + v.y + v.z + v.w;
    }
#pragma unroll
    for (int s = 16; s; s >>= 1) sum += __shfl_xor_sync(0xffffffffu, sum, s);
    if (lane == 0) {
        int kk = c * (PH * PH) + ph * PH + pw;
        ((float*)g_pp)[kk * BATCH + b] = (float)sum * (1.0f / 261120.0f);
    }
}

// ---------------------------------------------------------------------------
// Kernel 2 (FROZEN NUMERICS per chain): all 5 Eigen kc=248 panels run
// CONCURRENTLY (grid.z = panel). Each block: ascending-k fused-FMA chain
// per (batch, n) from 0 over its panel -> g_part[panel]. 2-column register
// blocking (n, n+12600), BT=32. 990 blocks -> ~16 warps/SM.
// ---------------------------------------------------------------------------
__global__ void __launch_bounds__(128) gemm_panel_kernel(const float* __restrict__ W) {
    __shared__ ull p_s[KCMAX][PAIRS];        // 31.7 KB
    int pan = blockIdx.z;
    int k0  = pan * KCMAX;
    int len = (pan == NPANEL - 1) ? (KDIM - 4 * KCMAX) : KCMAX;   // 208 last
    int n0 = blockIdx.x * 128 + threadIdx.x; // col 0: [0, 12600)
    int pbase = blockIdx.y * PAIRS;          // this block's 16 pairs
    bool active = (n0 < NHALF);
    int n1 = n0 + NHALF;                     // col 1: [12600, 25200)

    // coalesced tile fill: 128 B contiguous per k row
    for (int idx = threadIdx.x; idx < len * PAIRS; idx += 128) {
        int kk = idx >> 4, pp = idx & 15;
        p_s[kk][pp] = g_pp[(k0 + kk) * NPAIRS + pbase + pp];
    }
    __syncthreads();

    ull acc0[PAIRS], acc1[PAIRS];
#pragma unroll
    for (int i = 0; i < PAIRS; i++) { acc0[i] = 0ull; acc1[i] = 0ull; }

    if (active) {
        const float* wpa = W + (long)k0 * NTOT + n0;
        const float* wpb = W + (long)k0 * NTOT + n1;
        for (int kk = 0; kk < len; kk += 4) {
            float a0 = wpa[0];
            float a1 = wpa[NTOT];
            float a2 = wpa[2 * NTOT];
            float a3 = wpa[3 * NTOT];
            float c0 = wpb[0];
            float c1 = wpb[NTOT];
            float c2 = wpb[2 * NTOT];
            float c3 = wpb[3 * NTOT];
            wpa += 4 * (long)NTOT;
            wpb += 4 * (long)NTOT;
            ull A0 = dup2(a0), A1 = dup2(a1), A2 = dup2(a2), A3 = dup2(a3);
            ull C0 = dup2(c0), C1 = dup2(c1), C2 = dup2(c2), C3 = dup2(c3);
#pragma unroll
            for (int h = 0; h < PAIRS / 2; h++) {
                ulonglong2 q0 = *(const ulonglong2*)&p_s[kk + 0][2 * h];
                ulonglong2 q1 = *(const ulonglong2*)&p_s[kk + 1][2 * h];
                ulonglong2 q2 = *(const ulonglong2*)&p_s[kk + 2][2 * h];
                ulonglong2 q3 = *(const ulonglong2*)&p_s[kk + 3][2 * h];
                // strictly ascending k per accumulator chain (FROZEN)
                fma2(acc0[2 * h], q0.x, A0);
                fma2(acc0[2 * h], q1.x, A1);
                fma2(acc0[2 * h], q2.x, A2);
                fma2(acc0[2 * h], q3.x, A3);
                fma2(acc0[2 * h + 1], q0.y, A0);
                fma2(acc0[2 * h + 1], q1.y, A1);
                fma2(acc0[2 * h + 1], q2.y, A2);
                fma2(acc0[2 * h + 1], q3.y, A3);
                fma2(acc1[2 * h], q0.x, C0);
                fma2(acc1[2 * h], q1.x, C1);
                fma2(acc1[2 * h], q2.x, C2);
                fma2(acc1[2 * h], q3.x, C3);
                fma2(acc1[2 * h + 1], q0.y, C0);
                fma2(acc1[2 * h + 1], q1.y, C1);
                fma2(acc1[2 * h + 1], q2.y, C2);
                fma2(acc1[2 * h + 1], q3.y, C3);
            }
        }

        float* part = g_part[pan];
#pragma unroll
        for (int pp = 0; pp < PAIRS; pp++) {
            long rA = (long)(2 * (pbase + pp))     * NTOT;
            long rB = (long)(2 * (pbase + pp) + 1) * NTOT;
            float ya, yb;
            unpack2(acc0[pp], ya, yb);
            part[rA + n0] = ya; part[rB + n0] = yb;
            unpack2(acc1[pp], ya, yb);
            part[rA + n1] = ya; part[rB + n1] = yb;
        }
    }
}

// ---------------------------------------------------------------------------
// Kernel 3: score + argmax, one warp per (b,q) (19200 warps — full
// parallelism). y = ((((p0+p1)+p2)+p3)+p4) (FROZEN merge) per class col,
// then max/argmax over the 80 cols (ties -> lower index, matches argmax).
// ---------------------------------------------------------------------------
__global__ void score_kernel() {
    int warp = (blockIdx.x * blockDim.x + threadIdx.x) >> 5;
    int lane = threadIdx.x & 31;
    if (warp >= BATCH * NQ) return;
    long rowoff = (long)warp * NCCOLS;   // warp = b*NQ + q
    float best = -3.4e38f;
    int bidx = 0x7fffffff;
    for (int j = lane; j < 80; j += 32) {
        long e = rowoff + 4 + j;
        float v = g_part[0][e];          // FROZEN merge order
        v = v + g_part[1][e];
        v = v + g_part[2][e];
        v = v + g_part[3][e];
        v = v + g_part[4][e];
        if (v > best) { best = v; bidx = j; }
    }
#pragma unroll
    for (int s = 16; s; s >>= 1) {
        float ov = __shfl_xor_sync(0xffffffffu, best, s);
        int   oi = __shfl_xor_sync(0xffffffffu, bidx, s);
        if (ov > best || (ov == best && oi < bidx)) { best = ov; bidx = oi; }
    }
    if (lane == 0) { g_scores[warp] = best; g_ids[warp] = bidx; }
}

// ---------------------------------------------------------------------------
// Kernel 4: per-batch stable top-150 by rank counting (descending, ties by
// lower index — matches lax.top_k). Boxes merged from partials in FROZEN
// order. One block per batch, 320 threads.
// ---------------------------------------------------------------------------
__global__ void __launch_bounds__(320) topk_kernel(float* __restrict__ out) {
    __shared__ float s[NQ];
    int b = blockIdx.x;
    for (int q = threadIdx.x; q < NQ; q += 320) s[q] = g_scores[b * NQ + q];
    __syncthreads();
    int q = threadIdx.x;
    if (q < NQ) {
        float v = s[q];
        int rank = 0;
        for (int j = 0; j < NQ; j++) {
            float u = s[j];
            rank += (u > v) || (u == v && j < q);
        }
        if (rank < TOPK) {
            float* o = out + (long)(b * TOPK + rank) * 6;
            long rowoff = ((long)b * NQ + q) * NCCOLS;
#pragma unroll
            for (int c = 0; c < 4; c++) {
                float bx = g_part[0][rowoff + c];    // FROZEN merge order
                bx = bx + g_part[1][rowoff + c];
                bx = bx + g_part[2][rowoff + c];
                bx = bx + g_part[3][rowoff + c];
                bx = bx + g_part[4][rowoff + c];
                o[c] = bx;
            }
            o[4] = v;
            o[5] = (float)g_ids[b * NQ + q];
        }
    }
}

extern "C" void kernel_launch(void* const* d_in, const int* in_sizes, int n_in,
                              void* d_out, int out_size) {
    const int*   x = (const int*)d_in[0];
    const float* W = (const float*)d_in[1];
    float* out = (float*)d_out;

    pool_kernel<<<(BATCH * CH * PH * PH) / 8, 256>>>(x);

    dim3 gg((NHALF + 127) / 128, BATCH / BT, NPANEL);   // (99, 2, 5) = 990 blocks
    gemm_panel_kernel<<<gg, 128>>>(W);

    score_kernel<<<(BATCH * NQ * 32 + 255) / 256, 256>>>();
    topk_kernel<<<BATCH, 320>>>(out);
}